// round 5
// baseline (speedup 1.0000x reference)
#include <cuda_runtime.h>
#include <cstdint>

typedef unsigned long long ull;

// ---------------- scratch (device globals) ---------------------------------
__device__ float g_W2[1024 * 128];   // folded W for GEMM, [c][2e] DUPLICATED
__device__ float g_Wy[1024 * 64];    // folded bias-half, [d][e]
__device__ float g_imp[64];
__device__ unsigned int g_cnt[64];

#define PACK2(dst, f) asm("mov.b64 %0, {%1, %1};" : "=l"(dst) : "f"(f))
#define UNPACK2(lo, hi, src) asm("mov.b64 {%0, %1}, %2;" : "=f"(lo), "=f"(hi) : "l"(src))
#define FMA2(d, a, b, c) asm("fma.rn.f32x2 %0, %1, %2, %3;" : "=l"(d) : "l"(a), "l"(b), "l"(c))

// ---------------- kernel 1: fold full Wg@Wc (2048 cols, 128 blocks) --------
__global__ __launch_bounds__(256)
void k_prep(const float* __restrict__ Wg, const float* __restrict__ Wc, int C) {
    const int c0 = blockIdx.x * 16;          // [0, 2C)
    const int t = threadIdx.x;
    __shared__ float wg_s[64 * 65];
    __shared__ float wc_s[64 * 20];
    __shared__ float red[4 * 1024];
    if (blockIdx.x == 0 && t < 64) { g_imp[t] = 0.f; g_cnt[t] = 0u; }
    const int e = t & 63, ks = t >> 6;
    ull acc[8];
    #pragma unroll
    for (int p = 0; p < 8; ++p) acc[p] = 0ull;

    for (int kc = 0; kc < C; kc += 64) {
        #pragma unroll
        for (int r = 0; r < 16; ++r) {
            int idx = r * 256 + t;
            int ee = idx >> 6, j = idx & 63;
            wg_s[ee * 65 + j] = Wg[(size_t)ee * C + kc + j];
        }
        #pragma unroll
        for (int r = 0; r < 4; ++r) {
            int idx = r * 256 + t;
            int j = idx >> 4, i = idx & 15;
            wc_s[j * 20 + i] = Wc[(size_t)(kc + j) * (2 * C) + c0 + i];
        }
        __syncthreads();
        #pragma unroll
        for (int j = 0; j < 16; ++j) {
            int kk = ks * 16 + j;
            float w = wg_s[e * 65 + kk];
            ull w2; PACK2(w2, w);
            const ull* wc2 = (const ull*)(wc_s + kk * 20);
            #pragma unroll
            for (int p = 0; p < 8; ++p) FMA2(acc[p], w2, wc2[p], acc[p]);
        }
        __syncthreads();
    }
    #pragma unroll
    for (int p = 0; p < 8; ++p) {
        float lo, hi; UNPACK2(lo, hi, acc[p]);
        red[ks * 1024 + e * 16 + 2 * p]     = lo;
        red[ks * 1024 + e * 16 + 2 * p + 1] = hi;
    }
    __syncthreads();
    #pragma unroll
    for (int q = 0; q < 4; ++q) {
        int o = t * 4 + q;
        float v = red[o] + red[1024 + o] + red[2048 + o] + red[3072 + o];
        int ee = o >> 4, c = o & 15;
        int col = c0 + c;
        if (col < C) {
            g_W2[col * 128 + 2 * ee]     = v;
            g_W2[col * 128 + 2 * ee + 1] = v;
        } else {
            g_Wy[(col - C) * 64 + ee] = v;
        }
    }
}

// ---------------- kernel 2: main GEMM + bias + fused router epilogue -------
// 256 tokens/block, grid = BT/256. Token-pair f32x2, duplicated weights.
#define GKC 32

__global__ __launch_bounds__(256)
void k_main(const float* __restrict__ x, const float* __restrict__ cond,
            float* __restrict__ out, int BT, int T, int C) {
    extern __shared__ float dsm[];
    float* xs = dsm;                 // [GKC][256]  k-major, token fastest
    float* ws = dsm + GKC * 256;     // [GKC][128]  duplicated experts
    __shared__ float s_bp[256];
    __shared__ float s_bias[64];
    __shared__ float s_imp[64];
    __shared__ unsigned s_cnt[64];

    const int t = threadIdx.x;
    const int tok0 = blockIdx.x * 256;
    const int eg = t & 7, tg = t >> 3;
    const int batch = tok0 / T;      // 256 | T, so one batch per block
    const int nkt = C / GKC;

    if (t < 64) { s_imp[t] = 0.f; s_cnt[t] = 0u; }

    int myTok = tok0 + t; if (myTok >= BT) myTok = BT - 1;
    const float* xrow = x + (size_t)myTok * C;

    // prefetch tile 0
    float4 xf[8], wf[4];
    #pragma unroll
    for (int r = 0; r < 8; ++r) xf[r] = *(const float4*)(xrow + r * 4);
    #pragma unroll
    for (int r = 0; r < 4; ++r) wf[r] = ((const float4*)g_W2)[r * 256 + t];

    // bias row for this batch: bias[e] = sum_d g_Wy[d][e] * cond[batch][d]
    {
        const int e = t & 63, ks = t >> 6;
        const float* wy = g_Wy + (size_t)(ks * 256) * 64 + e;
        const float* cb = cond + (size_t)batch * C + ks * 256;
        float s = 0.f;
        #pragma unroll 4
        for (int d = 0; d < 256; ++d) s += wy[d * 64] * cb[d];
        s_bp[t] = s;
    }
    __syncthreads();
    if (t < 64) s_bias[t] = s_bp[t] + s_bp[t + 64] + s_bp[t + 128] + s_bp[t + 192];

    ull acc[4][8];
    #pragma unroll
    for (int p = 0; p < 4; ++p)
        #pragma unroll
        for (int j = 0; j < 8; ++j) acc[p][j] = 0ull;

    for (int kt = 0; kt < nkt; ++kt) {
        __syncthreads();
        #pragma unroll
        for (int r = 0; r < 8; ++r) {
            xs[(r * 4 + 0) * 256 + t] = xf[r].x;
            xs[(r * 4 + 1) * 256 + t] = xf[r].y;
            xs[(r * 4 + 2) * 256 + t] = xf[r].z;
            xs[(r * 4 + 3) * 256 + t] = xf[r].w;
        }
        #pragma unroll
        for (int r = 0; r < 4; ++r) ((float4*)ws)[r * 256 + t] = wf[r];
        __syncthreads();
        if (kt + 1 < nkt) {
            const float* xp = xrow + (kt + 1) * GKC;
            #pragma unroll
            for (int r = 0; r < 8; ++r) xf[r] = *(const float4*)(xp + r * 4);
            #pragma unroll
            for (int r = 0; r < 4; ++r)
                wf[r] = ((const float4*)g_W2)[(kt + 1) * 1024 + r * 256 + t];
        }
        #pragma unroll
        for (int k = 0; k < GKC; ++k) {
            const ull* wu = (const ull*)(ws + k * 128 + eg * 16);
            ull wr[8];
            #pragma unroll
            for (int j = 0; j < 8; ++j) wr[j] = wu[j];
            const ull* xu = (const ull*)(xs + k * 256 + tg * 8);
            ull xr[4];
            #pragma unroll
            for (int p = 0; p < 4; ++p) xr[p] = xu[p];
            #pragma unroll
            for (int p = 0; p < 4; ++p)
                #pragma unroll
                for (int j = 0; j < 8; ++j) FMA2(acc[p][j], wr[j], xr[p], acc[p][j]);
        }
    }

    // -------------------- epilogue --------------------
    const int e0 = eg * 8;
    float* out_idx = out;
    float* out_sc  = out + (size_t)BT * 2;
    float* out_pr  = out + (size_t)BT * 4;
    float imp[8] = {0.f, 0.f, 0.f, 0.f, 0.f, 0.f, 0.f, 0.f};
    float bj[8];
    #pragma unroll
    for (int j = 0; j < 8; ++j) bj[j] = s_bias[e0 + j];

    auto proc = [&](const float (&lv)[8], int tok) {
        // local top-2 (ties keep lower index)
        float v1 = -1e30f, v2 = -1e30f;
        int i1 = 0, i2 = 0;
        #pragma unroll
        for (int j = 0; j < 8; ++j) {
            float v = lv[j]; int ei = e0 + j;
            if (v > v1) { v2 = v1; i2 = i1; v1 = v; i1 = ei; }
            else if (v > v2) { v2 = v; i2 = ei; }
        }
        #pragma unroll
        for (int off = 1; off < 8; off <<= 1) {
            float ov1 = __shfl_xor_sync(0xffffffffu, v1, off);
            int   oi1 = __shfl_xor_sync(0xffffffffu, i1, off);
            float ov2 = __shfl_xor_sync(0xffffffffu, v2, off);
            int   oi2 = __shfl_xor_sync(0xffffffffu, i2, off);
            bool ob1 = (ov1 > v1) || (ov1 == v1 && oi1 < i1);
            if (ob1) {
                bool mb = (v1 > ov2) || (v1 == ov2 && i1 < oi2);
                if (mb) { v2 = v1; i2 = i1; } else { v2 = ov2; i2 = oi2; }
                v1 = ov1; i1 = oi1;
            } else {
                bool ob2 = (ov1 > v2) || (ov1 == v2 && oi1 < i2);
                if (ob2) { v2 = ov1; i2 = oi1; }
            }
        }
        // softmax over 64 (max == v1)
        float p[8], s = 0.f;
        #pragma unroll
        for (int j = 0; j < 8; ++j) { p[j] = __expf(lv[j] - v1); s += p[j]; }
        #pragma unroll
        for (int off = 1; off < 8; off <<= 1) s += __shfl_xor_sync(0xffffffffu, s, off);
        float inv = 1.0f / s;
        #pragma unroll
        for (int j = 0; j < 8; ++j) p[j] *= inv;

        if (tok < BT) {
            #pragma unroll
            for (int j = 0; j < 8; ++j) imp[j] += p[j];
            float4* pp = (float4*)(out_pr + (size_t)tok * 64 + e0);
            pp[0] = make_float4(p[0], p[1], p[2], p[3]);
            pp[1] = make_float4(p[4], p[5], p[6], p[7]);
            if (eg == 0) {
                out_idx[tok * 2]     = (float)i1;
                out_idx[tok * 2 + 1] = (float)i2;
                float s1 = 1.0f / (1.0f + __expf(v2 - v1));
                out_sc[tok * 2]     = s1;
                out_sc[tok * 2 + 1] = 1.0f - s1;
                atomicAdd(&s_cnt[i1], 1u);
                atomicAdd(&s_cnt[i2], 1u);
            }
        }
    };

    #pragma unroll
    for (int tp = 0; tp < 4; ++tp) {
        float la[8], lb[8];
        #pragma unroll
        for (int j = 0; j < 8; ++j) {
            float lo, hi; UNPACK2(lo, hi, acc[tp][j]);
            la[j] = lo + bj[j]; lb[j] = hi + bj[j];
        }
        int tok = tok0 + tg * 8 + 2 * tp;
        proc(la, tok);
        proc(lb, tok + 1);
    }

    #pragma unroll
    for (int j = 0; j < 8; ++j) atomicAdd(&s_imp[e0 + j], imp[j]);
    __syncthreads();
    if (t < 64) {
        atomicAdd(&g_imp[t], s_imp[t]);
        atomicAdd(&g_cnt[t], s_cnt[t]);
    }
}

// ---------------- kernel 3: finalize importance / load ---------------------
__global__ void k_final(float* __restrict__ out, int BT) {
    __shared__ float ssum;
    int e = threadIdx.x;
    if (e == 0) {
        float s = 0.f;
        for (int i = 0; i < 64; ++i) s += (float)g_cnt[i];
        ssum = s > 1.0f ? s : 1.0f;
    }
    __syncthreads();
    float* out_imp  = out + (size_t)BT * 4 + (size_t)BT * 64;
    float* out_load = out_imp + 64;
    if (e < 64) {
        out_imp[e]  = g_imp[e] / (float)BT;
        out_load[e] = (float)g_cnt[e] / ssum;
    }
}

// ---------------- launch ----------------------------------------------------
extern "C" void kernel_launch(void* const* d_in, const int* in_sizes, int n_in,
                              void* d_out, int out_size) {
    const float* x    = (const float*)d_in[0];
    const float* cond = (const float*)d_in[1];
    const float* Wg   = (const float*)d_in[2];
    const float* Wc   = (const float*)d_in[3];

    long long wcN = in_sizes[3];
    int C = 1;
    while ((long long)2 * C * C < wcN) C <<= 1;   // 1024
    int B = in_sizes[1] / C;                       // 4
    int T = in_sizes[0] / in_sizes[1];             // 8192
    int BT = B * T;

    size_t dsmem = (size_t)(GKC * 256 + GKC * 128) * sizeof(float);  // 48 KB
    cudaFuncSetAttribute(k_main, cudaFuncAttributeMaxDynamicSharedMemorySize, 65536);

    k_prep<<<2 * C / 16, 256>>>(Wg, Wc, C);
    k_main<<<(BT + 255) / 256, 256, dsmem>>>(x, cond, (float*)d_out, BT, T, C);
    k_final<<<1, 64>>>((float*)d_out, BT);
}